// round 5
// baseline (speedup 1.0000x reference)
#include <cuda_runtime.h>
#include <math.h>

#define BB  16
#define NQ  256
#define NKV 256
#define DD  64

__device__ float g_proj[BB * NKV * 3 * DD];

// ---- f32x2 packed helpers -------------------------------------------------
__device__ __forceinline__ unsigned long long pk2(float lo, float hi) {
    unsigned long long r;
    asm("mov.b64 %0, {%1, %2};" : "=l"(r) : "f"(lo), "f"(hi));
    return r;
}
__device__ __forceinline__ void upk2(unsigned long long v, float& lo, float& hi) {
    asm("mov.b64 {%0, %1}, %2;" : "=f"(lo), "=f"(hi) : "l"(v));
}
__device__ __forceinline__ unsigned long long fma2(unsigned long long a,
                                                   unsigned long long b,
                                                   unsigned long long c) {
    unsigned long long r;
    asm("fma.rn.f32x2 %0, %1, %2, %3;" : "=l"(r) : "l"(a), "l"(b), "l"(c));
    return r;
}
__device__ __forceinline__ unsigned long long add2(unsigned long long a,
                                                   unsigned long long b) {
    unsigned long long r;
    asm("add.rn.f32x2 %0, %1, %2;" : "=l"(r) : "l"(a), "l"(b));
    return r;
}
__device__ __forceinline__ float ex2f(float x) {
    float r; asm("ex2.approx.ftz.f32 %0, %1;" : "=f"(r) : "f"(x)); return r;
}

// ---------------------------------------------------------------------------
// Kernel A (persistent): proj = v_equi @ W_coord^T  (12288 rows of 64).
// 4 rows per warp per iteration (8 FMA per Wt LDS.64), next quad prefetched.
// ---------------------------------------------------------------------------
__global__ void __launch_bounds__(128) proj_kernel(const float* __restrict__ v,
                                                   const float* __restrict__ Wc) {
    __shared__ __align__(16) float Wt[64 * 66];      // Wt[e*66 + d] = Wc[d*64 + e]
    __shared__ __align__(16) float vbuf[4][4][64];   // [warp][row][e]

    int t = threadIdx.x;
    int w = t >> 5, l = t & 31;

    const int NQUAD = (BB * NKV * 3) / 4;            // 3072
    const int STRIDE = 296 * 4;
    int qd = blockIdx.x * 4 + w;

    float2 v0 = ((const float2*)(v + (size_t)(qd * 4 + 0) * 64))[l];
    float2 v1 = ((const float2*)(v + (size_t)(qd * 4 + 1) * 64))[l];
    float2 v2 = ((const float2*)(v + (size_t)(qd * 4 + 2) * 64))[l];
    float2 v3 = ((const float2*)(v + (size_t)(qd * 4 + 3) * 64))[l];

    for (int i = t; i < 4096; i += 128) {
        Wt[(i & 63) * 66 + (i >> 6)] = Wc[i];
    }
    __syncthreads();

    for (; qd < NQUAD; qd += STRIDE) {
        vbuf[w][0][2 * l] = v0.x;  vbuf[w][0][2 * l + 1] = v0.y;
        vbuf[w][1][2 * l] = v1.x;  vbuf[w][1][2 * l + 1] = v1.y;
        vbuf[w][2][2 * l] = v2.x;  vbuf[w][2][2 * l + 1] = v2.y;
        vbuf[w][3][2 * l] = v3.x;  vbuf[w][3][2 * l + 1] = v3.y;
        __syncwarp();

        int qn = qd + STRIDE;
        if (qn < NQUAD) {
            v0 = ((const float2*)(v + (size_t)(qn * 4 + 0) * 64))[l];
            v1 = ((const float2*)(v + (size_t)(qn * 4 + 1) * 64))[l];
            v2 = ((const float2*)(v + (size_t)(qn * 4 + 2) * 64))[l];
            v3 = ((const float2*)(v + (size_t)(qn * 4 + 3) * 64))[l];
        }

        float ax[4] = {0.f, 0.f, 0.f, 0.f};
        float ay[4] = {0.f, 0.f, 0.f, 0.f};
        #pragma unroll
        for (int e4 = 0; e4 < 16; e4++) {
            float4 va[4];
            #pragma unroll
            for (int r = 0; r < 4; r++) va[r] = *(const float4*)&vbuf[w][r][e4 * 4];
            #pragma unroll
            for (int i = 0; i < 4; i++) {
                float2 wt = *(const float2*)(Wt + (e4 * 4 + i) * 66 + 2 * l);
                #pragma unroll
                for (int r = 0; r < 4; r++) {
                    float fr = ((const float*)&va[r])[i];
                    ax[r] = fmaf(fr, wt.x, ax[r]);
                    ay[r] = fmaf(fr, wt.y, ay[r]);
                }
            }
        }
        #pragma unroll
        for (int r = 0; r < 4; r++) {
            ((float2*)(g_proj + (size_t)(qd * 4 + r) * 64))[l] = make_float2(ax[r], ay[r]);
        }
        __syncwarp();
    }
}

// ---------------------------------------------------------------------------
// Main kernel. CTA = (b, 4 q); warp owns one q. Half-warp-k layout (li=l&15
// owns a d-quad, h=l>>4 picks the pair member). msg ring holds 4 pairs ->
// prefetch distance 2 iterations (~300cy, covers DRAM); proj double-buffered
// at 1-iteration distance (covers L2). All accumulation in packed f32x2.
// ---------------------------------------------------------------------------
__global__ void __launch_bounds__(128, 6) attn_kernel(const float* __restrict__ msg,
                                                      const int*   __restrict__ adjm,
                                                      const float* __restrict__ Wa,
                                                      float*       __restrict__ out) {
    __shared__ __align__(16) float Wt[64 * 65];      // Wt[e*65 + d] = Wa[d*64 + e]
    __shared__ __align__(16) float ao[12][64];       // [q_local*3 + c][e]
    __shared__ __align__(16) unsigned short klist[4][NKV + 16];

    int t = threadIdx.x;
    int w = t >> 5, l = t & 31;
    int li = l & 15, h = l >> 4;
    int b = blockIdx.x >> 6;
    int qbase = (blockIdx.x & 63) << 2;
    int q = qbase + w;

    for (int i = t; i < 4096; i += 128) {
        Wt[(i & 63) * 65 + (i >> 6)] = Wa[i];
    }

    // build mask + compact active-k list
    const int* arow = adjm + (b * NQ + q) * NKV;
    unsigned mask[8];
    unsigned any = 0u;
    #pragma unroll
    for (int c = 0; c < 8; c++) {
        mask[c] = __ballot_sync(0xffffffffu, arow[c * 32 + l] != 0);
        any |= mask[c];
    }
    if (!any) {
        #pragma unroll
        for (int c = 0; c < 8; c++) mask[c] = 0xffffffffu;
    }
    int cnt = 0;
    #pragma unroll
    for (int c = 0; c < 8; c++) {
        unsigned m = mask[c];
        if ((m >> l) & 1u) {
            klist[w][cnt + __popc(m & ((1u << l) - 1u))] = (unsigned short)(c * 32 + l);
        }
        cnt += __popc(m);
    }
    __syncwarp();
    if (l < 16) klist[w][cnt + l] = klist[w][cnt - 1];   // pad (cnt >= 1 always)
    __syncwarp();

    const ulonglong2* msgU  = (const ulonglong2*)msg + (size_t)(b * NQ + q) * (NKV * 16);
    const ulonglong2* projU = (const ulonglong2*)g_proj + (size_t)b * (NKV * 48);

    const unsigned long long L2E2 = pk2(1.4426950408889634f, 1.4426950408889634f);

    unsigned long long dn01 = 0ull, dn23 = 0ull;
    unsigned long long w201 = 0ull, w223 = 0ull;
    unsigned long long a001 = 0ull, a023 = 0ull;
    unsigned long long a101 = 0ull, a123 = 0ull;
    unsigned long long a201 = 0ull, a223 = 0ull;

    // prologue: msg pairs 0,2,4,6 ; proj pairs 0,2
    int k0 = klist[w][0 + h], k1 = klist[w][2 + h];
    int k2 = klist[w][4 + h], k3 = klist[w][6 + h];
    ulonglong2 M0 = msgU[k0 * 16 + li];
    ulonglong2 M1 = msgU[k1 * 16 + li];
    ulonglong2 M2 = msgU[k2 * 16 + li];
    ulonglong2 M3 = msgU[k3 * 16 + li];
    ulonglong2 P0a = projU[k0 * 48 + li];
    ulonglong2 P0b = projU[k0 * 48 + 16 + li];
    ulonglong2 P0c = projU[k0 * 48 + 32 + li];
    ulonglong2 P1a = projU[k1 * 48 + li];
    ulonglong2 P1b = projU[k1 * 48 + 16 + li];
    ulonglong2 P1c = projU[k1 * 48 + 32 + li];
    int iq0 = k2, iq1 = k3;

#define CONSUME(P, M, PA, PB, PC)                                            \
    do {                                                                      \
        float addf = (((P) + h) < cnt) ? 0.f : -1e30f;                        \
        unsigned long long av = pk2(addf, addf);                              \
        unsigned long long t01 = fma2((M).x, L2E2, av);                       \
        unsigned long long t23 = fma2((M).y, L2E2, av);                       \
        float f0, f1, f2, f3;                                                 \
        upk2(t01, f0, f1); upk2(t23, f2, f3);                                 \
        unsigned long long e01 = pk2(ex2f(f0), ex2f(f1));                     \
        unsigned long long e23 = pk2(ex2f(f2), ex2f(f3));                     \
        dn01 = add2(dn01, e01); dn23 = add2(dn23, e23);                       \
        w201 = fma2(e01, e01, w201); w223 = fma2(e23, e23, w223);             \
        a001 = fma2(e01, (PA).x, a001); a023 = fma2(e23, (PA).y, a023);       \
        a101 = fma2(e01, (PB).x, a101); a123 = fma2(e23, (PB).y, a123);       \
        a201 = fma2(e01, (PC).x, a201); a223 = fma2(e23, (PC).y, a223);       \
    } while (0)

    #pragma unroll 2
    for (int j = 0; j < cnt; j += 4) {
        // indices for msg pairs j+8, j+10 (one LDS.64)
        ushort4 kn = *(const ushort4*)&klist[w][j + 8];
        int kn0 = h ? (int)kn.y : (int)kn.x;
        int kn1 = h ? (int)kn.w : (int)kn.z;
        // far msg prefetch (distance 2 iterations)
        ulonglong2 Mn0 = msgU[kn0 * 16 + li];
        ulonglong2 Mn1 = msgU[kn1 * 16 + li];
        // consume pair j, then load its proj replacement (pair j+4)
        CONSUME(j, M0, P0a, P0b, P0c);
        ulonglong2 Q0a = projU[iq0 * 48 + li];
        ulonglong2 Q0b = projU[iq0 * 48 + 16 + li];
        ulonglong2 Q0c = projU[iq0 * 48 + 32 + li];
        // consume pair j+2, then load pair j+6's proj
        CONSUME(j + 2, M1, P1a, P1b, P1c);
        ulonglong2 Q1a = projU[iq1 * 48 + li];
        ulonglong2 Q1b = projU[iq1 * 48 + 16 + li];
        ulonglong2 Q1c = projU[iq1 * 48 + 32 + li];
        // rotate rings
        M0 = M2; M1 = M3; M2 = Mn0; M3 = Mn1;
        P0a = Q0a; P0b = Q0b; P0c = Q0c;
        P1a = Q1a; P1b = Q1b; P1c = Q1c;
        iq0 = kn0; iq1 = kn1;
    }
#undef CONSUME

    // unpack accumulators
    float dn[4], w2[4], a0[4], a1[4], a2[4];
    upk2(dn01, dn[0], dn[1]); upk2(dn23, dn[2], dn[3]);
    upk2(w201, w2[0], w2[1]); upk2(w223, w2[2], w2[3]);
    upk2(a001, a0[0], a0[1]); upk2(a023, a0[2], a0[3]);
    upk2(a101, a1[0], a1[1]); upk2(a123, a1[2], a1[3]);
    upk2(a201, a2[0], a2[1]); upk2(a223, a2[2], a2[3]);

    // combine the two half-warp k-partitions
    #pragma unroll
    for (int i = 0; i < 4; i++) {
        dn[i] += __shfl_down_sync(0xffffffffu, dn[i], 16);
        w2[i] += __shfl_down_sync(0xffffffffu, w2[i], 16);
        a0[i] += __shfl_down_sync(0xffffffffu, a0[i], 16);
        a1[i] += __shfl_down_sync(0xffffffffu, a1[i], 16);
        a2[i] += __shfl_down_sync(0xffffffffu, a2[i], 16);
    }

    if (h == 0) {
        // attn_out = acc * sqrt(w2) / den^2
        #pragma unroll
        for (int i = 0; i < 4; i++) {
            float s = sqrtf(w2[i]) / (dn[i] * dn[i]);
            ao[w * 3 + 0][li * 4 + i] = a0[i] * s;
            ao[w * 3 + 1][li * 4 + i] = a1[i] * s;
            ao[w * 3 + 2][li * 4 + i] = a2[i] * s;
        }
    }
    __syncthreads();

    // epilogue: out[(q,c),d] = sum_e ao[(q,c)][e] * Wa[d][e]
    int d = t & 63;
    int half = t >> 6;
    float acc[6];
    const float* aop[6];
    #pragma unroll
    for (int jj = 0; jj < 6; jj++) {
        acc[jj] = 0.f;
        aop[jj] = &ao[0][0] + (half + 2 * jj) * 64;
    }
    #pragma unroll 4
    for (int e = 0; e < 64; e++) {
        float wt = Wt[e * 65 + d];
        #pragma unroll
        for (int jj = 0; jj < 6; jj++) {
            acc[jj] = fmaf(aop[jj][e], wt, acc[jj]);
        }
    }
    float* orow = out + ((size_t)(b * NQ + qbase) * 3) * 64;
    #pragma unroll
    for (int jj = 0; jj < 6; jj++) {
        int r = half + 2 * jj;          // r = q_local*3 + c
        orow[r * 64 + d] = acc[jj];
    }
}

extern "C" void kernel_launch(void* const* d_in, const int* in_sizes, int n_in,
                              void* d_out, int out_size) {
    const float* v_equi   = (const float*)d_in[0];
    const float* messages = (const float*)d_in[1];
    const int*   adj_mask = (const int*)d_in[2];
    const float* W_coord  = (const float*)d_in[3];
    const float* W_attn   = (const float*)d_in[4];
    float* out = (float*)d_out;

    proj_kernel<<<296, 128>>>(v_equi, W_coord);
    attn_kernel<<<BB * (NQ / 4), 128>>>(messages, adj_mask, W_attn, out);
}

// round 6
// speedup vs baseline: 1.3464x; 1.3464x over previous
#include <cuda_runtime.h>
#include <math.h>

#define BB  16
#define NQ  256
#define NKV 256
#define DD  64

__device__ float g_proj[BB * NKV * 3 * DD];

// ---------------------------------------------------------------------------
// Kernel A: proj = v_equi @ W_coord^T  (12288 rows of 64). grid=768, one
// 4-row quad per warp; v loads issued before Wt staging to overlap.
// ---------------------------------------------------------------------------
__global__ void __launch_bounds__(128) proj_kernel(const float* __restrict__ v,
                                                   const float* __restrict__ Wc) {
    __shared__ __align__(16) float Wt[64 * 66];      // Wt[e*66 + d] = Wc[d*64 + e]
    __shared__ __align__(16) float vbuf[4][4][64];   // [warp][row][e]

    int t = threadIdx.x;
    int w = t >> 5, l = t & 31;
    int qd = blockIdx.x * 4 + w;                     // 768*4 = 3072 quads exactly

    float2 v0 = ((const float2*)(v + (size_t)(qd * 4 + 0) * 64))[l];
    float2 v1 = ((const float2*)(v + (size_t)(qd * 4 + 1) * 64))[l];
    float2 v2 = ((const float2*)(v + (size_t)(qd * 4 + 2) * 64))[l];
    float2 v3 = ((const float2*)(v + (size_t)(qd * 4 + 3) * 64))[l];

    for (int i = t; i < 4096; i += 128) {
        Wt[(i & 63) * 66 + (i >> 6)] = Wc[i];
    }

    vbuf[w][0][2 * l] = v0.x;  vbuf[w][0][2 * l + 1] = v0.y;
    vbuf[w][1][2 * l] = v1.x;  vbuf[w][1][2 * l + 1] = v1.y;
    vbuf[w][2][2 * l] = v2.x;  vbuf[w][2][2 * l + 1] = v2.y;
    vbuf[w][3][2 * l] = v3.x;  vbuf[w][3][2 * l + 1] = v3.y;
    __syncthreads();

    float ax[4] = {0.f, 0.f, 0.f, 0.f};
    float ay[4] = {0.f, 0.f, 0.f, 0.f};
    #pragma unroll
    for (int e4 = 0; e4 < 16; e4++) {
        float4 va[4];
        #pragma unroll
        for (int r = 0; r < 4; r++) va[r] = *(const float4*)&vbuf[w][r][e4 * 4];
        #pragma unroll
        for (int i = 0; i < 4; i++) {
            float2 wt = *(const float2*)(Wt + (e4 * 4 + i) * 66 + 2 * l);
            #pragma unroll
            for (int r = 0; r < 4; r++) {
                float fr = ((const float*)&va[r])[i];
                ax[r] = fmaf(fr, wt.x, ax[r]);
                ay[r] = fmaf(fr, wt.y, ay[r]);
            }
        }
    }
    #pragma unroll
    for (int r = 0; r < 4; r++) {
        ((float2*)(g_proj + (size_t)(qd * 4 + r) * 64))[l] = make_float2(ax[r], ay[r]);
    }
}

// ---------------------------------------------------------------------------
// Main kernel. CTA = (b, 4 q); warp owns one q. Half-warp-k layout: li=l&15
// owns a d-quad, h=l>>4 picks the pair member. msg is streamed GMEM->SMEM via
// cp.async (2-slot ring, depth = 2 iterations = 8 k's in flight, zero register
// cost, zero scoreboard stalls); proj loaded direct from L2, issued before the
// cp.async wait so the wait covers its latency.
// ---------------------------------------------------------------------------
__global__ void __launch_bounds__(128, 7) attn_kernel(const float* __restrict__ msg,
                                                      const int*   __restrict__ adjm,
                                                      const float* __restrict__ Wa,
                                                      float*       __restrict__ out) {
    __shared__ __align__(16) float Wt[64 * 65];      // Wt[e*65 + d] = Wa[d*64 + e]
    __shared__ __align__(16) float ao[12][64];       // [q_local*3 + c][e]
    __shared__ __align__(16) unsigned short klist[4][NKV + 16];
    __shared__ __align__(16) float4 ring[4][2][2][2][16];  // [warp][slot][pair][h][li]

    int t = threadIdx.x;
    int w = t >> 5, l = t & 31;
    int li = l & 15, h = l >> 4;
    int b = blockIdx.x >> 6;
    int qbase = (blockIdx.x & 63) << 2;
    int q = qbase + w;

    for (int i = t; i < 4096; i += 128) {
        Wt[(i & 63) * 65 + (i >> 6)] = Wa[i];
    }

    // build mask + compact active-k list
    const int* arow = adjm + (b * NQ + q) * NKV;
    unsigned mask[8];
    unsigned any = 0u;
    #pragma unroll
    for (int c = 0; c < 8; c++) {
        mask[c] = __ballot_sync(0xffffffffu, arow[c * 32 + l] != 0);
        any |= mask[c];
    }
    if (!any) {
        #pragma unroll
        for (int c = 0; c < 8; c++) mask[c] = 0xffffffffu;
    }
    int cnt = 0;
    #pragma unroll
    for (int c = 0; c < 8; c++) {
        unsigned m = mask[c];
        if ((m >> l) & 1u) {
            klist[w][cnt + __popc(m & ((1u << l) - 1u))] = (unsigned short)(c * 32 + l);
        }
        cnt += __popc(m);
    }
    __syncwarp();
    if (l < 16) klist[w][cnt + l] = klist[w][cnt - 1];   // pad (cnt >= 1 always)
    __syncwarp();

    const float4* msg4  = (const float4*)msg + (size_t)(b * NQ + q) * (NKV * 16);
    const float4* proj4 = (const float4*)g_proj + (size_t)b * (NKV * 48);

    float dn[4] = {0.f, 0.f, 0.f, 0.f};
    float w2[4] = {0.f, 0.f, 0.f, 0.f};
    float a0[4] = {0.f, 0.f, 0.f, 0.f};
    float a1[4] = {0.f, 0.f, 0.f, 0.f};
    float a2[4] = {0.f, 0.f, 0.f, 0.f};

#define CP_ISSUE(slot, kk0, kk1)                                               \
    do {                                                                       \
        unsigned d0 = (unsigned)__cvta_generic_to_shared(&ring[w][slot][0][h][li]); \
        unsigned d1 = (unsigned)__cvta_generic_to_shared(&ring[w][slot][1][h][li]); \
        const float4* s0 = msg4 + (kk0) * 16 + li;                             \
        const float4* s1 = msg4 + (kk1) * 16 + li;                             \
        asm volatile("cp.async.cg.shared.global [%0], [%1], 16;" :: "r"(d0), "l"(s0) : "memory"); \
        asm volatile("cp.async.cg.shared.global [%0], [%1], 16;" :: "r"(d1), "l"(s1) : "memory"); \
        asm volatile("cp.async.commit_group;" ::: "memory");                   \
    } while (0)

    // prologue: indices for iterations 0 and 1, issue both groups
    ushort4 kq0 = *(const ushort4*)&klist[w][0];
    int ka0 = h ? (int)kq0.y : (int)kq0.x;
    int ka1 = h ? (int)kq0.w : (int)kq0.z;
    ushort4 kq1 = *(const ushort4*)&klist[w][4];
    int kb0 = h ? (int)kq1.y : (int)kq1.x;
    int kb1 = h ? (int)kq1.w : (int)kq1.z;
    CP_ISSUE(0, ka0, ka1);
    CP_ISSUE(1, kb0, kb1);

    int niter = (cnt + 3) >> 2;
    for (int i = 0; i < niter; i++) {
        int slot = i & 1;
        // proj loads first (their latency is covered by the cp.async wait)
        float4 p00 = proj4[ka0 * 48 + li];
        float4 p01 = proj4[ka0 * 48 + 16 + li];
        float4 p02 = proj4[ka0 * 48 + 32 + li];
        float4 p10 = proj4[ka1 * 48 + li];
        float4 p11 = proj4[ka1 * 48 + 16 + li];
        float4 p12 = proj4[ka1 * 48 + 32 + li];
        // next-next iteration's indices
        ushort4 kq = *(const ushort4*)&klist[w][4 * i + 8];
        int kn0 = h ? (int)kq.y : (int)kq.x;
        int kn1 = h ? (int)kq.w : (int)kq.z;

        asm volatile("cp.async.wait_group 1;" ::: "memory");
        float4 m0 = ring[w][slot][0][h][li];
        float4 m1 = ring[w][slot][1][h][li];

        // pair 0 (k elements 4i+h)
        {
            float f = (4 * i + h < cnt) ? 1.f : 0.f;
            float e0 = __expf(m0.x) * f;
            float e1 = __expf(m0.y) * f;
            float e2 = __expf(m0.z) * f;
            float e3 = __expf(m0.w) * f;
            dn[0] += e0; dn[1] += e1; dn[2] += e2; dn[3] += e3;
            w2[0] = fmaf(e0, e0, w2[0]); w2[1] = fmaf(e1, e1, w2[1]);
            w2[2] = fmaf(e2, e2, w2[2]); w2[3] = fmaf(e3, e3, w2[3]);
            a0[0] = fmaf(e0, p00.x, a0[0]); a0[1] = fmaf(e1, p00.y, a0[1]);
            a0[2] = fmaf(e2, p00.z, a0[2]); a0[3] = fmaf(e3, p00.w, a0[3]);
            a1[0] = fmaf(e0, p01.x, a1[0]); a1[1] = fmaf(e1, p01.y, a1[1]);
            a1[2] = fmaf(e2, p01.z, a1[2]); a1[3] = fmaf(e3, p01.w, a1[3]);
            a2[0] = fmaf(e0, p02.x, a2[0]); a2[1] = fmaf(e1, p02.y, a2[1]);
            a2[2] = fmaf(e2, p02.z, a2[2]); a2[3] = fmaf(e3, p02.w, a2[3]);
        }
        // pair 1 (k elements 4i+2+h)
        {
            float f = (4 * i + 2 + h < cnt) ? 1.f : 0.f;
            float e0 = __expf(m1.x) * f;
            float e1 = __expf(m1.y) * f;
            float e2 = __expf(m1.z) * f;
            float e3 = __expf(m1.w) * f;
            dn[0] += e0; dn[1] += e1; dn[2] += e2; dn[3] += e3;
            w2[0] = fmaf(e0, e0, w2[0]); w2[1] = fmaf(e1, e1, w2[1]);
            w2[2] = fmaf(e2, e2, w2[2]); w2[3] = fmaf(e3, e3, w2[3]);
            a0[0] = fmaf(e0, p10.x, a0[0]); a0[1] = fmaf(e1, p10.y, a0[1]);
            a0[2] = fmaf(e2, p10.z, a0[2]); a0[3] = fmaf(e3, p10.w, a0[3]);
            a1[0] = fmaf(e0, p11.x, a1[0]); a1[1] = fmaf(e1, p11.y, a1[1]);
            a1[2] = fmaf(e2, p11.z, a1[2]); a1[3] = fmaf(e3, p11.w, a1[3]);
            a2[0] = fmaf(e0, p12.x, a2[0]); a2[1] = fmaf(e1, p12.y, a2[1]);
            a2[2] = fmaf(e2, p12.z, a2[2]); a2[3] = fmaf(e3, p12.w, a2[3]);
        }

        // refill this slot for iteration i+2 (consumed data already in regs)
        CP_ISSUE(slot, kn0, kn1);
        ka0 = kb0; ka1 = kb1; kb0 = kn0; kb1 = kn1;
    }
    asm volatile("cp.async.wait_group 0;" ::: "memory");
#undef CP_ISSUE

    // combine the two half-warp k-partitions
    #pragma unroll
    for (int i = 0; i < 4; i++) {
        dn[i] += __shfl_down_sync(0xffffffffu, dn[i], 16);
        w2[i] += __shfl_down_sync(0xffffffffu, w2[i], 16);
        a0[i] += __shfl_down_sync(0xffffffffu, a0[i], 16);
        a1[i] += __shfl_down_sync(0xffffffffu, a1[i], 16);
        a2[i] += __shfl_down_sync(0xffffffffu, a2[i], 16);
    }

    if (h == 0) {
        // attn_out = acc * sqrt(w2) / den^2
        #pragma unroll
        for (int i = 0; i < 4; i++) {
            float s = sqrtf(w2[i]) / (dn[i] * dn[i]);
            ao[w * 3 + 0][li * 4 + i] = a0[i] * s;
            ao[w * 3 + 1][li * 4 + i] = a1[i] * s;
            ao[w * 3 + 2][li * 4 + i] = a2[i] * s;
        }
    }
    __syncthreads();

    // epilogue: out[(q,c),d] = sum_e ao[(q,c)][e] * Wa[d][e]
    int d = t & 63;
    int half = t >> 6;
    float acc[6];
    const float* aop[6];
    #pragma unroll
    for (int jj = 0; jj < 6; jj++) {
        acc[jj] = 0.f;
        aop[jj] = &ao[0][0] + (half + 2 * jj) * 64;
    }
    #pragma unroll 4
    for (int e = 0; e < 64; e++) {
        float wt = Wt[e * 65 + d];
        #pragma unroll
        for (int jj = 0; jj < 6; jj++) {
            acc[jj] = fmaf(aop[jj][e], wt, acc[jj]);
        }
    }
    float* orow = out + ((size_t)(b * NQ + qbase) * 3) * 64;
    #pragma unroll
    for (int jj = 0; jj < 6; jj++) {
        int r = half + 2 * jj;          // r = q_local*3 + c
        orow[r * 64 + d] = acc[jj];
    }
}

extern "C" void kernel_launch(void* const* d_in, const int* in_sizes, int n_in,
                              void* d_out, int out_size) {
    const float* v_equi   = (const float*)d_in[0];
    const float* messages = (const float*)d_in[1];
    const int*   adj_mask = (const int*)d_in[2];
    const float* W_coord  = (const float*)d_in[3];
    const float* W_attn   = (const float*)d_in[4];
    float* out = (float*)d_out;

    proj_kernel<<<768, 128>>>(v_equi, W_coord);
    attn_kernel<<<BB * (NQ / 4), 128>>>(messages, adj_mask, W_attn, out);
}